// round 9
// baseline (speedup 1.0000x reference)
#include <cuda_runtime.h>

#define BB    32
#define CINN  16
#define COUTT 32
#define HH    14
#define WW    14
#define KK    5
#define OHH   5
#define OWW   5
#define HWSZ  (HH*WW)        // 196
#define IMG   (HWSZ*HWSZ)    // 38416
#define IMG4  (IMG/4)        // 9604
#define TS_W  169            // only (h2,w2) in [0,13)^2 are used by conv2
#define NPAIR (COUTT/2)      // 16 channel pairs

#define RED_BLOCKS   ((BB * IMG4 + 255) / 256)           // 1201
#define USUM_ELEMS   (BB * HWSZ)                          // 6272
#define USUM_BLOCKS  ((USUM_ELEMS + 255) / 256)           // 25

// Scratch (global device arrays; no allocations)
__device__ float g_Csum[BB * IMG];                        // 4.9 MB (L2-resident)
__device__ float g_T[(size_t)BB * COUTT * 25 * TS_W];     // 17.3 MB (L2-resident)
__device__ float g_usum[USUM_ELEMS];                      // 25 KB

// ---- packed f32x2 helpers (Blackwell FFMA2) --------------------------------
__device__ __forceinline__ unsigned long long pack2(float lo, float hi) {
    unsigned long long r;
    asm("mov.b64 %0, {%1, %2};" : "=l"(r) : "f"(lo), "f"(hi));
    return r;
}
__device__ __forceinline__ unsigned long long bcast2(float v) {
    unsigned long long r;
    asm("mov.b64 %0, {%1, %1};" : "=l"(r) : "f"(v));
    return r;
}
__device__ __forceinline__ void fma2(unsigned long long& d,
                                     unsigned long long a,
                                     unsigned long long b) {
    asm("fma.rn.f32x2 %0, %1, %2, %0;" : "+l"(d) : "l"(a), "l"(b));
}
__device__ __forceinline__ void unpack2(unsigned long long v, float& lo, float& hi) {
    asm("mov.b64 {%0, %1}, %2;" : "=f"(lo), "=f"(hi) : "l"(v));
}

// ---------------------------------------------------------------------------
// Kernel 1: blocks [0,1201):  Csum[b,hw2,hw4] = sum_c C[b,c,...]  (78.7 MB)
//           blocks [1201,1226): usum[b,hw]    = sum_c u[b,c,hw]   (0.4 MB)
// ---------------------------------------------------------------------------
__global__ void reduce_c_kernel(const float4* __restrict__ C4,
                                const float* __restrict__ u) {
    if (blockIdx.x < RED_BLOCKS) {
        int idx = blockIdx.x * blockDim.x + threadIdx.x;
        if (idx >= BB * IMG4) return;
        int b = idx / IMG4;
        int j = idx - b * IMG4;
        const float4* p = C4 + (size_t)b * CINN * IMG4 + j;
        float ax = 0.f, ay = 0.f, az = 0.f, aw = 0.f;
#pragma unroll
        for (int c = 0; c < CINN; c++) {
            float4 v = __ldcs(p + (size_t)c * IMG4);   // streaming: evict-first
            ax += v.x; ay += v.y; az += v.z; aw += v.w;
        }
        reinterpret_cast<float4*>(g_Csum)[idx] = make_float4(ax, ay, az, aw);
    } else {
        int t = (blockIdx.x - RED_BLOCKS) * blockDim.x + threadIdx.x;
        if (t >= USUM_ELEMS) return;
        int b  = t / HWSZ;
        int hw = t - b * HWSZ;
        const float* up = u + (size_t)b * CINN * HWSZ + hw;
        float a = 0.f;
#pragma unroll
        for (int c = 0; c < CINN; c++) a += up[c * HWSZ];
        g_usum[t] = a;
    }
}

// ---------------------------------------------------------------------------
// Kernel 2: first conv (dims 4,5), all 32 channels, only 169 needed (h2,w2).
// FFMA2: channels in pairs.  T[b][i][p][j] = sum_k w[i,k]*Csum[b,j,win_p(k)]
// grid = (25, B), block = 192 (tid<169 active)
// ---------------------------------------------------------------------------
__global__ void conv1_kernel(const float* __restrict__ w) {
    __shared__ unsigned long long ws2[25 * NPAIR];   // [k][ipair]
    int tid = threadIdx.x;

    for (int t = tid; t < 25 * NPAIR; t += blockDim.x) {
        int k  = t / NPAIR;
        int ip = t - k * NPAIR;
        ws2[t] = pack2(w[(2 * ip) * 25 + k], w[(2 * ip + 1) * 25 + k]);
    }
    __syncthreads();

    int yx = blockIdx.x;              // p = y1*5+x1
    int b  = blockIdx.y;
    int y1 = yx / OWW, x1 = yx - y1 * OWW;

    if (tid < TS_W) {
        int h2 = tid / 13, w2 = tid - h2 * 13;
        const float* src = g_Csum + (size_t)b * IMG + (h2 * WW + w2) * HWSZ
                           + (2 * y1) * WW + 2 * x1;
        unsigned long long patch2[25];
#pragma unroll
        for (int r = 0; r < KK; r++)
#pragma unroll
            for (int c = 0; c < KK; c++)
                patch2[r * KK + c] = bcast2(__ldg(src + r * WW + c));

        float* dst = g_T + (((size_t)b * COUTT) * 25 + yx) * TS_W + tid;
#pragma unroll
        for (int ip = 0; ip < NPAIR; ip++) {
            unsigned long long acc = 0ull;
#pragma unroll
            for (int k = 0; k < 25; k++)
                fma2(acc, patch2[k], ws2[k * NPAIR + ip]);
            float lo, hi;
            unpack2(acc, lo, hi);
            dst[(size_t)(2 * ip)     * 25 * TS_W] = lo;   // coalesced over tid
            dst[(size_t)(2 * ip + 1) * 25 * TS_W] = hi;
        }
    }
}

// ---------------------------------------------------------------------------
// Kernel 3: second conv (dims 2,3) + fused mean path.
// out_cov[b,i,q,p] = sum_a w[i,a] * T[b,i,p,win_q(a)]
// out_mean[b,i,y,x] = sum_a w[i,a] * usum[b, win_{y,x}(a)]
// grid = B*COUT, block = 640 (tid<625 cov, then tid<25 mean)
// ---------------------------------------------------------------------------
__global__ void conv2_kernel(const float* __restrict__ w,
                             float* __restrict__ out_cov,
                             float* __restrict__ out_mean) {
    __shared__ float Ts[25 * TS_W];   // 16.9 KB
    __shared__ float ws[25];
    __shared__ float us[HWSZ];
    int tid = threadIdx.x;
    int bi  = blockIdx.x;             // b*32 + i
    int i   = bi % COUTT;
    int b   = bi / COUTT;

    const float* tsrc = g_T + (size_t)bi * 25 * TS_W;
    for (int k = tid; k < 25 * TS_W; k += blockDim.x) Ts[k] = tsrc[k];
    if (tid < 25) ws[tid] = w[i * 25 + tid];
    if (tid >= 32 && tid < 32 + HWSZ) us[tid - 32] = g_usum[b * HWSZ + (tid - 32)];
    __syncthreads();

    if (tid < 625) {
        int q = tid / 25;             // y2*5+x2
        int p = tid - q * 25;         // y1*5+x1
        int y2 = q / OWW, x2 = q - y2 * OWW;
        const float* base = Ts + p * TS_W + (2 * y2) * 13 + 2 * x2;
        float acc = 0.f;
#pragma unroll
        for (int r = 0; r < KK; r++)
#pragma unroll
            for (int c = 0; c < KK; c++)
                acc += ws[r * KK + c] * base[r * 13 + c];
        out_cov[(size_t)bi * 625 + tid] = acc;   // coalesced
    }

    if (tid < 25) {                   // mean outputs for this (b,i)
        int y = tid / OWW, x = tid - y * OWW;
        const float* base = us + (2 * y) * WW + 2 * x;
        float acc = 0.f;
#pragma unroll
        for (int r = 0; r < KK; r++)
#pragma unroll
            for (int c = 0; c < KK; c++)
                acc += ws[r * KK + c] * base[r * WW + c];
        out_mean[(size_t)bi * 25 + tid] = acc;
    }
}

// ---------------------------------------------------------------------------
extern "C" void kernel_launch(void* const* d_in, const int* in_sizes, int n_in,
                              void* d_out, int out_size) {
    const float* u = (const float*)d_in[0];   // [32,16,14,14]
    const float* C = (const float*)d_in[1];   // [32,16,14,14,14,14]
    const float* w = (const float*)d_in[2];   // [32,1,5,5]
    float* out      = (float*)d_out;
    float* out_mean = out;                               // 25600 floats
    float* out_cov  = out + BB * COUTT * OHH * OWW;      // 640000 floats

    // 1) channel reductions (C: HBM-bound; u: appended blocks)
    reduce_c_kernel<<<RED_BLOCKS + USUM_BLOCKS, 256>>>((const float4*)C, u);

    // 2) first conv (dims 4,5), FFMA2, 169 needed positions
    dim3 g1(OHH * OWW, BB);
    conv1_kernel<<<g1, 192>>>(w);

    // 3) second conv (dims 2,3) + fused mean path
    conv2_kernel<<<BB * COUTT, 640>>>(w, out_cov, out_mean);
}

// round 10
// speedup vs baseline: 1.0131x; 1.0131x over previous
#include <cuda_runtime.h>

#define BB    32
#define CINN  16
#define COUTT 32
#define HH    14
#define WW    14
#define KK    5
#define OHH   5
#define OWW   5
#define HWSZ  (HH*WW)        // 196
#define IMG   (HWSZ*HWSZ)    // 38416
#define IMG4  (IMG/4)        // 9604
#define TS_W  169            // only (h2,w2) in [0,13)^2 are used by conv2
#define NPAIR (COUTT/2)      // 16 channel pairs

#define RED_BLOCKS   ((BB * IMG4 + 255) / 256)           // 1201
#define USUM_ELEMS   (BB * HWSZ)                          // 6272
#define USUM_BLOCKS  ((USUM_ELEMS + 255) / 256)           // 25

// Scratch (global device arrays; no allocations)
__device__ float g_Csum[BB * IMG];                        // 4.9 MB (L2-resident)
__device__ float g_T[(size_t)BB * COUTT * 25 * TS_W];     // 17.3 MB (L2-resident)
__device__ float g_usum[USUM_ELEMS];                      // 25 KB

// ---- packed f32x2 helpers (Blackwell FFMA2) --------------------------------
__device__ __forceinline__ unsigned long long pack2(float lo, float hi) {
    unsigned long long r;
    asm("mov.b64 %0, {%1, %2};" : "=l"(r) : "f"(lo), "f"(hi));
    return r;
}
__device__ __forceinline__ unsigned long long bcast2(float v) {
    unsigned long long r;
    asm("mov.b64 %0, {%1, %1};" : "=l"(r) : "f"(v));
    return r;
}
__device__ __forceinline__ void fma2(unsigned long long& d,
                                     unsigned long long a,
                                     unsigned long long b) {
    asm("fma.rn.f32x2 %0, %1, %2, %0;" : "+l"(d) : "l"(a), "l"(b));
}
__device__ __forceinline__ void unpack2(unsigned long long v, float& lo, float& hi) {
    asm("mov.b64 {%0, %1}, %2;" : "=f"(lo), "=f"(hi) : "l"(v));
}

// ---------------------------------------------------------------------------
// Kernel 1: blocks [0,1201):  Csum[b,hw2,hw4] = sum_c C[b,c,...]  (78.7 MB)
//           blocks [1201,1226): usum[b,hw]    = sum_c u[b,c,hw]   (0.4 MB)
// ---------------------------------------------------------------------------
__global__ void reduce_c_kernel(const float4* __restrict__ C4,
                                const float* __restrict__ u) {
    if (blockIdx.x < RED_BLOCKS) {
        int idx = blockIdx.x * blockDim.x + threadIdx.x;
        if (idx >= BB * IMG4) return;
        int b = idx / IMG4;
        int j = idx - b * IMG4;
        const float4* p = C4 + (size_t)b * CINN * IMG4 + j;
        float ax = 0.f, ay = 0.f, az = 0.f, aw = 0.f;
#pragma unroll
        for (int c = 0; c < CINN; c++) {
            float4 v = __ldcs(p + (size_t)c * IMG4);   // streaming: evict-first
            ax += v.x; ay += v.y; az += v.z; aw += v.w;
        }
        reinterpret_cast<float4*>(g_Csum)[idx] = make_float4(ax, ay, az, aw);
    } else {
        int t = (blockIdx.x - RED_BLOCKS) * blockDim.x + threadIdx.x;
        if (t >= USUM_ELEMS) return;
        int b  = t / HWSZ;
        int hw = t - b * HWSZ;
        const float* up = u + (size_t)b * CINN * HWSZ + hw;
        float a = 0.f;
#pragma unroll
        for (int c = 0; c < CINN; c++) a += up[c * HWSZ];
        g_usum[t] = a;
    }
}

// ---------------------------------------------------------------------------
// Kernel 2: first conv (dims 4,5), all 32 channels, only 169 needed (h2,w2).
// FFMA2: channels in pairs.  T[b][i][p][j] = sum_k w[i,k]*Csum[b,j,win_p(k)]
// grid = (25, B), block = 192 (tid<169 active)
// ---------------------------------------------------------------------------
__global__ void conv1_kernel(const float* __restrict__ w) {
    __shared__ unsigned long long ws2[25 * NPAIR];   // [k][ipair]
    int tid = threadIdx.x;

    for (int t = tid; t < 25 * NPAIR; t += blockDim.x) {
        int k  = t / NPAIR;
        int ip = t - k * NPAIR;
        ws2[t] = pack2(w[(2 * ip) * 25 + k], w[(2 * ip + 1) * 25 + k]);
    }
    __syncthreads();

    int yx = blockIdx.x;              // p = y1*5+x1
    int b  = blockIdx.y;
    int y1 = yx / OWW, x1 = yx - y1 * OWW;

    if (tid < TS_W) {
        int h2 = tid / 13, w2 = tid - h2 * 13;
        const float* src = g_Csum + (size_t)b * IMG + (h2 * WW + w2) * HWSZ
                           + (2 * y1) * WW + 2 * x1;
        unsigned long long patch2[25];
#pragma unroll
        for (int r = 0; r < KK; r++)
#pragma unroll
            for (int c = 0; c < KK; c++)
                patch2[r * KK + c] = bcast2(__ldg(src + r * WW + c));

        float* dst = g_T + (((size_t)b * COUTT) * 25 + yx) * TS_W + tid;
#pragma unroll
        for (int ip = 0; ip < NPAIR; ip++) {
            unsigned long long acc = 0ull;
#pragma unroll
            for (int k = 0; k < 25; k++)
                fma2(acc, patch2[k], ws2[k * NPAIR + ip]);
            float lo, hi;
            unpack2(acc, lo, hi);
            dst[(size_t)(2 * ip)     * 25 * TS_W] = lo;   // coalesced over tid
            dst[(size_t)(2 * ip + 1) * 25 * TS_W] = hi;
        }
    }
}

// ---------------------------------------------------------------------------
// Kernel 3: second conv (dims 2,3) + fused mean path.
// out_cov[b,i,q,p] = sum_a w[i,a] * T[b,i,p,win_q(a)]
// out_mean[b,i,y,x] = sum_a w[i,a] * usum[b, win_{y,x}(a)]
// grid = B*COUT, block = 640 (tid<625 cov, then tid<25 mean)
// ---------------------------------------------------------------------------
__global__ void conv2_kernel(const float* __restrict__ w,
                             float* __restrict__ out_cov,
                             float* __restrict__ out_mean) {
    __shared__ float Ts[25 * TS_W];   // 16.9 KB
    __shared__ float ws[25];
    __shared__ float us[HWSZ];
    int tid = threadIdx.x;
    int bi  = blockIdx.x;             // b*32 + i
    int i   = bi % COUTT;
    int b   = bi / COUTT;

    const float* tsrc = g_T + (size_t)bi * 25 * TS_W;
    for (int k = tid; k < 25 * TS_W; k += blockDim.x) Ts[k] = tsrc[k];
    if (tid < 25) ws[tid] = w[i * 25 + tid];
    if (tid >= 32 && tid < 32 + HWSZ) us[tid - 32] = g_usum[b * HWSZ + (tid - 32)];
    __syncthreads();

    if (tid < 625) {
        int q = tid / 25;             // y2*5+x2
        int p = tid - q * 25;         // y1*5+x1
        int y2 = q / OWW, x2 = q - y2 * OWW;
        const float* base = Ts + p * TS_W + (2 * y2) * 13 + 2 * x2;
        float acc = 0.f;
#pragma unroll
        for (int r = 0; r < KK; r++)
#pragma unroll
            for (int c = 0; c < KK; c++)
                acc += ws[r * KK + c] * base[r * 13 + c];
        out_cov[(size_t)bi * 625 + tid] = acc;   // coalesced
    }

    if (tid < 25) {                   // mean outputs for this (b,i)
        int y = tid / OWW, x = tid - y * OWW;
        const float* base = us + (2 * y) * WW + 2 * x;
        float acc = 0.f;
#pragma unroll
        for (int r = 0; r < KK; r++)
#pragma unroll
            for (int c = 0; c < KK; c++)
                acc += ws[r * KK + c] * base[r * WW + c];
        out_mean[(size_t)bi * 25 + tid] = acc;
    }
}

// ---------------------------------------------------------------------------
extern "C" void kernel_launch(void* const* d_in, const int* in_sizes, int n_in,
                              void* d_out, int out_size) {
    const float* u = (const float*)d_in[0];   // [32,16,14,14]
    const float* C = (const float*)d_in[1];   // [32,16,14,14,14,14]
    const float* w = (const float*)d_in[2];   // [32,1,5,5]
    float* out      = (float*)d_out;
    float* out_mean = out;                               // 25600 floats
    float* out_cov  = out + BB * COUTT * OHH * OWW;      // 640000 floats

    // 1) channel reductions (C: HBM-bound; u: appended blocks)
    reduce_c_kernel<<<RED_BLOCKS + USUM_BLOCKS, 256>>>((const float4*)C, u);

    // 2) first conv (dims 4,5), FFMA2, 169 needed positions
    dim3 g1(OHH * OWW, BB);
    conv1_kernel<<<g1, 192>>>(w);

    // 3) second conv (dims 2,3) + fused mean path
    conv2_kernel<<<BB * COUTT, 640>>>(w, out_cov, out_mean);
}